// round 3
// baseline (speedup 1.0000x reference)
#include <cuda_runtime.h>

#define HH 56
#define WW 56
#define CIN 128
#define NP 4
#define NG 2
#define NL 32

__global__ __launch_bounds__(256, 1)
void fused_shuffle_conv(const float* __restrict__ x,   // [128,56,56]
                        const float* __restrict__ w0,  // [32,2,3,3]
                        const float* __restrict__ w1,  // [4,64]
                        float* __restrict__ out)       // [128,56,56]
{
    __shared__ float xs[CIN][WW];           // 28672 B  : one H-row of x
    __shared__ float t4s[NP][NG][WW + 4];   // 1920 B   : mixed channels, padded by 2 each side
    __shared__ float W5s[NL][NG][5];        // 1280 B   : collapsed 5-tap kernel
    __shared__ float w0s[NL * NG * 9];      // 2304 B
    __shared__ float w1s[NP][64];           // 1024 B

    const int h   = blockIdx.x;
    const int tid = threadIdx.x;

    // ---- load weights ----
    for (int i = tid; i < NL * NG * 9; i += blockDim.x) w0s[i] = w0[i];
    for (int i = tid; i < NP * 64; i += blockDim.x) (&w1s[0][0])[i] = w1[i];

    // ---- Phase A: load x row h, vectorized (56 f32 = 14 float4 per channel) ----
    for (int i = tid; i < CIN * 14; i += blockDim.x) {
        int c = i / 14, v = i % 14;
        float4 val = ((const float4*)(x + (size_t)c * HH * WW + h * WW))[v];
        ((float4*)&xs[c][0])[v] = val;
    }

    // zero the W-padding of t4s (positions 0,1 and W+2,W+3)
    if (tid < NP * NG * 4) {
        int p = tid / (NG * 4);
        int r = tid % (NG * 4);
        int g = r / 4, e = r % 4;
        int idx = (e < 2) ? e : (WW + e);   // 0,1,58,59
        t4s[p][g][idx] = 0.f;
    }
    __syncthreads();

    // ---- build W5[l][g][d] = sum_{u1+u2=d} w0[l,g,u1,u2]  (320 entries > 256 threads:
    //      MUST grid-stride — this was the R1 correctness bug) ----
    for (int i = tid; i < NL * NG * 5; i += blockDim.x) {
        int l = i / (NG * 5);
        int r = i % (NG * 5);
        int g = r / 5, d = r % 5;
        float s = 0.f;
        #pragma unroll
        for (int u1 = 0; u1 < 3; u1++) {
            int u2 = d - u1;
            if (u2 >= 0 && u2 < 3) s += w0s[(l * NG + g) * 9 + u1 * 3 + u2];
        }
        W5s[l][g][d] = s;
    }

    // ---- Phase B: t4[p,g,w] = sum_c x[2c+g, w] * w1[p][c]  (112 threads, 4 accums) ----
    if (tid < NG * WW) {
        int g = tid / WW, w = tid % WW;
        float a0 = 0.f, a1 = 0.f, a2 = 0.f, a3 = 0.f;
        #pragma unroll 8
        for (int c = 0; c < 64; c++) {
            float xv = xs[2 * c + g][w];
            a0 += xv * w1s[0][c];
            a1 += xv * w1s[1][c];
            a2 += xv * w1s[2][c];
            a3 += xv * w1s[3][c];
        }
        t4s[0][g][w + 2] = a0;
        t4s[1][g][w + 2] = a1;
        t4s[2][g][w + 2] = a2;
        t4s[3][g][w + 2] = a3;
    }
    __syncthreads();

    // ---- Phase C: 1-D conv along W + boundary corrections + H-roll ----
    // 224 active threads: w = tid%56, quad q = tid/56; each handles l in {q, q+4, ..., q+28}, all p.
    const int hout = (h + 1) % HH;
    if (tid < 4 * WW) {
        const int w = tid % WW;
        const int q = tid / WW;

        // hoist all taps into registers: t4r[p][g][d] = t4s[p][g][w+d] = t4[p,g,h,w+d-2]
        float t4r[NP][NG][5];
        #pragma unroll
        for (int p = 0; p < NP; p++)
            #pragma unroll
            for (int g = 0; g < NG; g++)
                #pragma unroll
                for (int d = 0; d < 5; d++)
                    t4r[p][g][d] = t4s[p][g][w + d];

        const bool bl = (w == 0);
        const bool br = (w == WW - 1);

        #pragma unroll
        for (int li = 0; li < 8; li++) {
            const int l = q + li * 4;
            float W5r[NG][5];
            #pragma unroll
            for (int g = 0; g < NG; g++)
                #pragma unroll
                for (int d = 0; d < 5; d++)
                    W5r[g][d] = W5s[l][g][d];

            // boundary corrections (mask lives on u2):
            //   w==0  : subtract w0[l,g,2,0] * t4[p,g,h,0]   (= t4r[p][g][2])
            //   w==55 : subtract w0[l,g,0,2] * t4[p,g,h,55]  (= t4r[p][g][2])
            float cg0 = 0.f, cg1 = 0.f;
            if (bl) { cg0 = w0s[(l * NG + 0) * 9 + 6]; cg1 = w0s[(l * NG + 1) * 9 + 6]; }
            if (br) { cg0 = w0s[(l * NG + 0) * 9 + 2]; cg1 = w0s[(l * NG + 1) * 9 + 2]; }

            #pragma unroll
            for (int p = 0; p < NP; p++) {
                float acc = 0.f;
                #pragma unroll
                for (int g = 0; g < NG; g++)
                    #pragma unroll
                    for (int d = 0; d < 5; d++)
                        acc += W5r[g][d] * t4r[p][g][d];
                acc -= cg0 * t4r[p][0][2] + cg1 * t4r[p][1][2];
                out[(size_t)(l * 4 + p) * HH * WW + hout * WW + w] = acc;
            }
        }
    }
}

extern "C" void kernel_launch(void* const* d_in, const int* in_sizes, int n_in,
                              void* d_out, int out_size)
{
    const float* x  = (const float*)d_in[0];   // [1,128,56,56]
    const float* w0 = (const float*)d_in[1];   // [32,2,3,3]
    const float* w1 = (const float*)d_in[2];   // [4,64]
    float* out = (float*)d_out;                // [1,128,56,56]

    fused_shuffle_conv<<<HH, 256>>>(x, w0, w1, out);
}

// round 4
// speedup vs baseline: 1.3155x; 1.3155x over previous
#include <cuda_runtime.h>

#define HH 56
#define WW 56
#define CHW (HH * WW)   // 3136

// grid = 224 blocks: bid = h*4 + p.  Block computes t4[p,g,0:56] for row h
// and the 32 output channels {l*4+p} of output row (h+1)%56.
__global__ __launch_bounds__(224)
void fused_shuffle_conv(const float* __restrict__ x,   // [128,56,56]
                        const float* __restrict__ w0,  // [32,2,3,3]
                        const float* __restrict__ w1,  // [4,64]
                        float* __restrict__ out)       // [128,56,56]
{
    __shared__ float t4part[2][2][WW];   // [half][g][w] partial channel-mix sums
    __shared__ float t4s[2][WW + 4];     // [g][w+2], zero-padded 2 each side
    __shared__ float W5s[32][2][5];      // collapsed 5-tap kernel

    const int bid = blockIdx.x;
    const int h   = bid >> 2;
    const int p   = bid & 3;
    const int tid = threadIdx.x;

    // ---- Phase B (partial): t4part[half][g][w] = sum_{c in half} x[2c+g,h,w] * w1[p,c]
    //      Direct coalesced LDG from x; w1 reads are warp-uniform (broadcast).
    {
        const int half = tid / 112;            // 0 or 1 -> c in [32*half, 32*half+32)
        const int r    = tid % 112;
        const int g    = r / WW;
        const int w    = r % WW;
        const float* xp  = x + (size_t)g * CHW + (size_t)h * WW + w;
        const float* w1p = w1 + p * 64 + half * 32;
        float acc = 0.f;
        #pragma unroll
        for (int c = 0; c < 32; c++) {
            int cc = half * 32 + c;
            acc += xp[(size_t)(2 * cc) * CHW] * w1p[c];
        }
        t4part[half][g][w] = acc;
    }

    // ---- W5[l][g][d] = sum_{u1+u2=d} w0[l,g,u1,u2]  (320 entries, grid-stride; reads
    //      global w0 directly — warp-mostly-uniform, L1/L2 cached). Overlaps Phase B.
    for (int i = tid; i < 32 * 2 * 5; i += blockDim.x) {
        int l = i / 10;
        int r = i % 10;
        int g = r / 5, d = r % 5;
        const float* w0lg = w0 + (l * 2 + g) * 9;
        float s = 0.f;
        #pragma unroll
        for (int u1 = 0; u1 < 3; u1++) {
            int u2 = d - u1;
            if (u2 >= 0 && u2 < 3) s += w0lg[u1 * 3 + u2];
        }
        W5s[l][g][d] = s;
    }

    // ---- zero t4s W-padding (positions 0,1,58,59 per g) ----
    if (tid < 8) {
        int g = tid >> 2, e = tid & 3;
        t4s[g][(e < 2) ? e : (WW + e)] = 0.f;
    }

    __syncthreads();

    // ---- combine the two c-half partials ----
    if (tid < 2 * WW) {
        int g = tid / WW, w = tid % WW;
        t4s[g][w + 2] = t4part[0][g][w] + t4part[1][g][w];
    }

    __syncthreads();

    // ---- Phase C: 5-tap conv along W + boundary corrections + H-roll ----
    // 224 threads: w = tid%56, q = tid/56; thread handles l = q, q+4, ..., q+28.
    {
        const int w = tid % WW;
        const int q = tid / WW;
        const int hout = (h + 1) % HH;

        float t4r[2][5];
        #pragma unroll
        for (int g = 0; g < 2; g++)
            #pragma unroll
            for (int d = 0; d < 5; d++)
                t4r[g][d] = t4s[g][w + d];

        const bool bl = (w == 0);
        const bool br = (w == WW - 1);

        #pragma unroll
        for (int li = 0; li < 8; li++) {
            const int l = q + li * 4;
            float acc = 0.f;
            #pragma unroll
            for (int g = 0; g < 2; g++)
                #pragma unroll
                for (int d = 0; d < 5; d++)
                    acc += W5s[l][g][d] * t4r[g][d];

            // boundary corrections (mask on u2 of the second unfold):
            //   w==0  : subtract w0[l,g,2,0]*t4[g,w=0];  w==55: subtract w0[l,g,0,2]*t4[g,w=55]
            if (bl | br) {
                int off = bl ? 6 : 2;
                float cg0 = __ldg(w0 + (l * 2 + 0) * 9 + off);
                float cg1 = __ldg(w0 + (l * 2 + 1) * 9 + off);
                acc -= cg0 * t4r[0][2] + cg1 * t4r[1][2];
            }
            out[(size_t)(l * 4 + p) * CHW + (size_t)hout * WW + w] = acc;
        }
    }
}

extern "C" void kernel_launch(void* const* d_in, const int* in_sizes, int n_in,
                              void* d_out, int out_size)
{
    const float* x  = (const float*)d_in[0];   // [1,128,56,56]
    const float* w0 = (const float*)d_in[1];   // [32,2,3,3]
    const float* w1 = (const float*)d_in[2];   // [4,64]
    float* out = (float*)d_out;                // [1,128,56,56]

    fused_shuffle_conv<<<HH * 4, 224>>>(x, w0, w1, out);
}